// round 4
// baseline (speedup 1.0000x reference)
#include <cuda_runtime.h>
#include <cuda_bf16.h>

// Problem constants
#define B_    8
#define H_    256
#define P_    225          // H - KER + 1
#define KER_  32
#define HALF_ 16
#define K_    2
#define CDA_  64
#define NBC_  16           // B * 2 classes
#define NRB_  15           // row-blocks per map (15 rows each)
#define NPOOLBLK_ (NBC_ * NRB_)   // 240

// Output section offsets (floats)
#define OFF_CLS   0
#define OFF_FEAT  65536
#define OFF_VALS  2162688
#define OFF_PES   2162720
#define OFF_TRUE  2195488
#define OFF_OXY   2228256

// Scratch
__device__ float g_rowsum[NBC_ * H_ * P_];
__device__ float g_pooled[NBC_ * P_ * P_];
__device__ float g_pval[NBC_ * NRB_];
__device__ int   g_pidx[NBC_ * NRB_];
__device__ int   g_selpx[NBC_ * K_];
__device__ int   g_selpy[NBC_ * K_];
__device__ unsigned int g_ticket = 0;

// ---------------------------------------------------------------------------
// Kernel 1: softmax over C=2 + horizontal 32-window sums via warp chunk-scans.
// win(x) = (S_w - scan_w[r-1]) + scan_{w+1}[r-1],  x = 32w + r.
// grid = B*H blocks, 256 threads.
// ---------------------------------------------------------------------------
__global__ void k_rowsum(const float* __restrict__ infeat) {
    int by = blockIdx.x;
    int b = by >> 8;
    int y = by & 255;
    int x = threadIdx.x;
    int lane = x & 31;

    __shared__ float sc0[H_];
    __shared__ float sc1[H_];

    float x0 = infeat[((b * 2 + 0) * H_ + y) * H_ + x];
    float x1 = infeat[((b * 2 + 1) * H_ + y) * H_ + x];
    float m  = fmaxf(x0, x1);
    float e0 = expf(x0 - m);
    float e1 = expf(x1 - m);
    float inv = 1.0f / (e0 + e1);
    float s0 = e0 * inv;
    float s1 = e1 * inv;

    // inclusive scan within each 32-chunk
#pragma unroll
    for (int o = 1; o < 32; o <<= 1) {
        float t0 = __shfl_up_sync(0xffffffffu, s0, o);
        float t1 = __shfl_up_sync(0xffffffffu, s1, o);
        if (lane >= o) { s0 += t0; s1 += t1; }
    }
    sc0[x] = s0;
    sc1[x] = s1;
    __syncthreads();

    if (x < P_) {
        int w = x >> 5, r = x & 31;
        float S0 = sc0[(w << 5) | 31];
        float S1 = sc1[(w << 5) | 31];
        float w0, w1;
        if (r == 0) {
            w0 = S0; w1 = S1;
        } else {
            w0 = (S0 - sc0[x - 1]) + sc0[x + 31];
            w1 = (S1 - sc1[x - 1]) + sc1[x + 31];
        }
        g_rowsum[((b * 2 + 0) * H_ + y) * P_ + x] = w0;
        g_rowsum[((b * 2 + 1) * H_ + y) * P_ + x] = w1;
    }
}

// ---------------------------------------------------------------------------
// Warp argmax combine: max value, lowest flat index on ties. All lanes get result.
// ---------------------------------------------------------------------------
__device__ __forceinline__ void warp_argmax(float& bv, int& bix) {
#pragma unroll
    for (int o = 16; o > 0; o >>= 1) {
        float ov = __shfl_xor_sync(0xffffffffu, bv, o);
        int   oi = __shfl_xor_sync(0xffffffffu, bix, o);
        if (ov > bv || (ov == bv && oi < bix)) { bv = ov; bix = oi; }
    }
}

// ---------------------------------------------------------------------------
// Kernel 2: vertical pooling + per-block argmax partial, with the greedy
// top-2 selection folded in as a last-block tail (threadfence + ticket).
// grid = (16 bc, 15 row-blocks), 256 threads.
// ---------------------------------------------------------------------------
__global__ void k_poolsel(float* __restrict__ out) {
    int bc = blockIdx.x;
    int chunk = blockIdx.y;
    int px = threadIdx.x;

    const float* rs = g_rowsum + bc * H_ * P_;
    float* outp = g_pooled + bc * P_ * P_;

    float best = -1e30f;
    int bi = 0x7fffffff;

    if (px < P_) {
        int py0 = chunk * 15;
        float s = 0.0f;
#pragma unroll
        for (int i = 0; i < KER_; i++) s += rs[(py0 + i) * P_ + px];
        float v = s * (1.0f / 1024.0f);
        outp[py0 * P_ + px] = v;
        best = v; bi = py0 * P_ + px;
#pragma unroll
        for (int q = 1; q < 15; q++) {
            int py = py0 + q;
            s += rs[(py + 31) * P_ + px] - rs[(py - 1) * P_ + px];
            v = s * (1.0f / 1024.0f);
            outp[py * P_ + px] = v;
            if (v > best) { best = v; bi = py * P_ + px; }
        }
    }

    __shared__ float sv[256];
    __shared__ int   si[256];
    sv[threadIdx.x] = best;
    si[threadIdx.x] = bi;
    __syncthreads();
    for (int s = 128; s > 0; s >>= 1) {
        if (threadIdx.x < s) {
            float ov = sv[threadIdx.x + s];
            int   oi = si[threadIdx.x + s];
            if (ov > sv[threadIdx.x] ||
                (ov == sv[threadIdx.x] && oi < si[threadIdx.x])) {
                sv[threadIdx.x] = ov; si[threadIdx.x] = oi;
            }
        }
        __syncthreads();
    }
    if (threadIdx.x == 0) {
        g_pval[bc * NRB_ + chunk] = sv[0];
        g_pidx[bc * NRB_ + chunk] = si[0];
    }

    // ---- last-block selection tail ----
    __shared__ unsigned int s_isLast;
    __syncthreads();                       // all writes above issued
    if (threadIdx.x == 0) {
        __threadfence();
        unsigned int t = atomicAdd(&g_ticket, 1u);
        s_isLast = (t == NPOOLBLK_ - 1) ? 1u : 0u;
    }
    __syncthreads();
    if (!s_isLast) return;

    int warp = threadIdx.x >> 5;
    int lane = threadIdx.x & 31;

    for (int mybc = warp; mybc < NBC_; mybc += 8) {
        int b = mybc >> 1;
        int c = mybc & 1;
        const float* pm = g_pooled + mybc * P_ * P_;

        // pass 1: reduce 15 partials
        float bv = -1e30f; int bix = 0x7fffffff;
        if (lane < NRB_) {
            bv  = g_pval[mybc * NRB_ + lane];
            bix = g_pidx[mybc * NRB_ + lane];
        }
        warp_argmax(bv, bix);
        int idx0 = bix;
        float val0 = bv;
        int py0 = idx0 / P_;
        int px0 = idx0 - py0 * P_;

        // pass 2: suppression rescan of affected row-blocks
        int lo  = max(0, py0 - HALF_), hi  = min(P_, py0 + HALF_);
        int clo = max(0, px0 - HALF_), chi = min(P_, px0 + HALF_);
        int rblo = lo / 15, rbhi = (hi - 1) / 15;
        int rlo = rblo * 15;
        int rhi = min(P_, (rbhi + 1) * 15);

        bv = -1e30f; bix = 0x7fffffff;
        if (lane < NRB_ && (lane < rblo || lane > rbhi)) {
            bv  = g_pval[mybc * NRB_ + lane];
            bix = g_pidx[mybc * NRB_ + lane];
        }
        for (int r = rlo; r < rhi; r++) {
            bool rin = (r >= lo && r < hi);
            int rowbase = r * P_;
            for (int cc = lane; cc < P_; cc += 32) {
                int idx = rowbase + cc;
                float v = pm[idx];
                if (rin && cc >= clo && cc < chi) v = 0.0f;
                if (v > bv || (v == bv && idx < bix)) { bv = v; bix = idx; }
            }
        }
        warp_argmax(bv, bix);

        if (lane == 0) {
            int idx1 = bix;
            float val1 = bv;
            int py1 = idx1 / P_;
            int px1 = idx1 - py1 * P_;

            int pxs[K_] = {px0, px1};
            int pys[K_] = {py0, py1};
            float vals[K_] = {val0, val1};
#pragma unroll
            for (int j = 0; j < K_; j++) {
                g_selpx[mybc * K_ + j] = pxs[j];
                g_selpy[mybc * K_ + j] = pys[j];
                out[OFF_VALS + (c * K_ + j) * B_ + b] = vals[j];
                int o = OFF_OXY + ((c * K_ + j) * B_ + b) * 4;
                out[o + 0] = (float)pxs[j];
                out[o + 1] = (float)(pxs[j] + KER_ - 1);
                out[o + 2] = (float)pys[j];
                out[o + 3] = (float)(pys[j] + KER_ - 1);
            }
        }
    }

    __syncthreads();
    if (threadIdx.x == 0) g_ticket = 0;   // reset for next launch
}

// ---------------------------------------------------------------------------
// Kernel 3: patch gather. 128 threads/block, 8 floats/thread:
// 8 independent scalar loads + 2 STG.128.
// ---------------------------------------------------------------------------
__global__ void k_extract(const float* __restrict__ infeat,
                          const float* __restrict__ pesudo,
                          const float* __restrict__ labelT,
                          const float* __restrict__ feat,
                          float* __restrict__ out) {
    int blk = blockIdx.x;
    const float* src;
    int Csrc, ch, c, j, b;
    long base;

    if (blk < 64) {
        int t = blk;
        ch = t & 1;  t >>= 1;
        b  = t & 7;  t >>= 3;
        j  = t & 1;  t >>= 1;
        c  = t;
        src = infeat; Csrc = 2;
        base = OFF_CLS + (long)blk * 1024;
    } else if (blk < 2112) {
        int t = blk - 64;
        int local = t;
        ch = t & 63; t >>= 6;
        b  = t & 7;  t >>= 3;
        j  = t & 1;  t >>= 1;
        c  = t;
        src = feat; Csrc = CDA_;
        base = OFF_FEAT + (long)local * 1024;
    } else if (blk < 2144) {
        int t = blk - 2112;
        int local = t;
        ch = 0;
        b  = t & 7;  t >>= 3;
        j  = t & 1;  t >>= 1;
        c  = t;
        src = pesudo; Csrc = 1;
        base = OFF_PES + (long)local * 1024;
    } else {
        int t = blk - 2144;
        int local = t;
        ch = 0;
        b  = t & 7;  t >>= 3;
        j  = t & 1;  t >>= 1;
        c  = t;
        src = labelT; Csrc = 1;
        base = OFF_TRUE + (long)local * 1024;
    }

    int sel = (b * 2 + c) * K_ + j;
    int px = g_selpx[sel];
    int py = g_selpy[sel];

    const float* s = src + (((long)b * Csrc + ch) * H_ + py) * H_ + px;

    int t = threadIdx.x;          // 128 threads, 8 consecutive floats each
    int dy = t >> 2;
    int dx = (t & 3) * 8;
    const float* sp = s + dy * H_ + dx;
    float4 va, vb;
    va.x = sp[0]; va.y = sp[1]; va.z = sp[2]; va.w = sp[3];
    vb.x = sp[4]; vb.y = sp[5]; vb.z = sp[6]; vb.w = sp[7];
    float* op = out + base + (long)t * 8;
    *reinterpret_cast<float4*>(op)     = va;
    *reinterpret_cast<float4*>(op + 4) = vb;
}

// ---------------------------------------------------------------------------
extern "C" void kernel_launch(void* const* d_in, const int* in_sizes, int n_in,
                              void* d_out, int out_size) {
    const float* infeat  = (const float*)d_in[0];
    const float* pesudo  = (const float*)d_in[1];
    const float* labelT  = (const float*)d_in[2];
    const float* featDA  = (const float*)d_in[3];
    float* out = (float*)d_out;

    k_rowsum<<<B_ * H_, 256>>>(infeat);
    dim3 g2(NBC_, NRB_);
    k_poolsel<<<g2, 256>>>(out);
    k_extract<<<2176, 128>>>(infeat, pesudo, labelT, featDA, out);
}

// round 5
// speedup vs baseline: 2.7639x; 2.7639x over previous
#include <cuda_runtime.h>
#include <cuda_bf16.h>

// Problem constants
#define B_    8
#define H_    256
#define P_    225          // H - KER + 1
#define KER_  32
#define HALF_ 16
#define K_    2
#define CDA_  64
#define NBC_  16           // B * 2 classes
#define NRB_  15           // row-blocks per map (15 rows each)
#define GRID_ 240          // persistent blocks = NBC_ * NRB_

// Output section offsets (floats)
#define OFF_CLS   0
#define OFF_FEAT  65536
#define OFF_VALS  2162688
#define OFF_PES   2162720
#define OFF_TRUE  2195488
#define OFF_OXY   2228256

// Scratch
__device__ float g_rowsum[NBC_ * H_ * P_];
__device__ float g_pooled[NBC_ * P_ * P_];
__device__ float g_pval[NBC_ * NRB_];
__device__ int   g_pidx[NBC_ * NRB_];
__device__ int   g_selpx[NBC_ * K_];
__device__ int   g_selpy[NBC_ * K_];

// Grid barrier state. g_cnt returns to 0 after each barrier; g_gen grows
// monotonically (comparisons are relative) -> deterministic across replays.
__device__ unsigned g_cnt = 0;
__device__ unsigned g_gen = 0;

__device__ __forceinline__ void gridbar() {
    __threadfence();               // make this thread's writes globally visible
    __syncthreads();               // all block threads fenced
    if (threadIdx.x == 0) {
        unsigned eg = atomicAdd(&g_gen, 0u);       // entry generation
        unsigned my = atomicAdd(&g_cnt, 1u);
        if (my == GRID_ - 1) {
            atomicExch(&g_cnt, 0u);
            __threadfence();
            atomicAdd(&g_gen, 1u);                 // release
        } else {
            while (atomicAdd(&g_gen, 0u) == eg) __nanosleep(64);
            __threadfence();
        }
    }
    __syncthreads();
}

__global__ void __launch_bounds__(256, 2)
k_fused(const float* __restrict__ infeat,
        const float* __restrict__ pesudo,
        const float* __restrict__ labelT,
        const float* __restrict__ feat,
        float* __restrict__ out) {
    __shared__ float sc0[H_];
    __shared__ float sc1[H_];
    __shared__ float sv[256];
    __shared__ int   si[256];

    const int tid = threadIdx.x;
    const int lane = tid & 31;
    const int blk = blockIdx.x;

    // ================= Phase A: softmax + horizontal 32-window sums =========
    // win(x) = (S_w - scan_w[r-1]) + scan_{w+1}[r-1], chunk scans via shfl.
    for (int by = blk; by < B_ * H_; by += GRID_) {
        int b = by >> 8;
        int y = by & 255;

        float x0 = infeat[((b * 2 + 0) * H_ + y) * H_ + tid];
        float x1 = infeat[((b * 2 + 1) * H_ + y) * H_ + tid];
        float m  = fmaxf(x0, x1);
        float e0 = expf(x0 - m);
        float e1 = expf(x1 - m);
        float inv = 1.0f / (e0 + e1);
        float s0 = e0 * inv;
        float s1 = e1 * inv;

#pragma unroll
        for (int o = 1; o < 32; o <<= 1) {
            float t0 = __shfl_up_sync(0xffffffffu, s0, o);
            float t1 = __shfl_up_sync(0xffffffffu, s1, o);
            if (lane >= o) { s0 += t0; s1 += t1; }
        }
        __syncthreads();           // previous iteration's readers done
        sc0[tid] = s0;
        sc1[tid] = s1;
        __syncthreads();

        if (tid < P_) {
            int w = tid >> 5, r = tid & 31;
            float S0 = sc0[(w << 5) | 31];
            float S1 = sc1[(w << 5) | 31];
            float w0, w1;
            if (r == 0) { w0 = S0; w1 = S1; }
            else {
                w0 = (S0 - sc0[tid - 1]) + sc0[tid + 31];
                w1 = (S1 - sc1[tid - 1]) + sc1[tid + 31];
            }
            g_rowsum[((b * 2 + 0) * H_ + y) * P_ + tid] = w0;
            g_rowsum[((b * 2 + 1) * H_ + y) * P_ + tid] = w1;
        }
    }

    gridbar();

    // ================= Phase B: vertical pooling + per-slab argmax ==========
    {
        int bc = blk / NRB_;
        int chunk = blk % NRB_;
        const float* rs = g_rowsum + bc * H_ * P_;
        float* outp = g_pooled + bc * P_ * P_;

        float best = -1e30f;
        int bi = 0x7fffffff;

        if (tid < P_) {
            int py0 = chunk * 15;
            float s = 0.0f;
#pragma unroll
            for (int i = 0; i < KER_; i++) s += rs[(py0 + i) * P_ + tid];
            float v = s * (1.0f / 1024.0f);
            outp[py0 * P_ + tid] = v;
            best = v; bi = py0 * P_ + tid;
            for (int py = py0 + 1; py < py0 + 15; py++) {
                s += rs[(py + 31) * P_ + tid] - rs[(py - 1) * P_ + tid];
                v = s * (1.0f / 1024.0f);
                outp[py * P_ + tid] = v;
                if (v > best) { best = v; bi = py * P_ + tid; }
            }
        }

        sv[tid] = best; si[tid] = bi;
        __syncthreads();
        for (int s = 128; s > 0; s >>= 1) {
            if (tid < s) {
                float ov = sv[tid + s];
                int   oi = si[tid + s];
                if (ov > sv[tid] || (ov == sv[tid] && oi < si[tid])) {
                    sv[tid] = ov; si[tid] = oi;
                }
            }
            __syncthreads();
        }
        if (tid == 0) {
            g_pval[bc * NRB_ + chunk] = sv[0];
            g_pidx[bc * NRB_ + chunk] = si[0];
        }
    }

    gridbar();

    // ================= Phase C: greedy top-2 selection (blocks 0..15) =======
    if (blk < NBC_) {
        int bc = blk;
        int b = bc >> 1;
        int c = bc & 1;
        const float* pm = g_pooled + bc * P_ * P_;

        // pass 1: reduce 15 partials
        float best = -1e30f;
        int bi = 0x7fffffff;
        if (tid < NRB_) {
            best = g_pval[bc * NRB_ + tid];
            bi   = g_pidx[bc * NRB_ + tid];
        }
        sv[tid] = best; si[tid] = bi;
        __syncthreads();
        for (int s = 128; s > 0; s >>= 1) {
            if (tid < s) {
                float ov = sv[tid + s];
                int   oi = si[tid + s];
                if (ov > sv[tid] || (ov == sv[tid] && oi < si[tid])) {
                    sv[tid] = ov; si[tid] = oi;
                }
            }
            __syncthreads();
        }
        int idx0 = si[0];
        float val0 = sv[0];
        int py0 = idx0 / P_;
        int px0 = idx0 - py0 * P_;
        __syncthreads();

        // pass 2: rescan affected row-blocks with suppression
        int lo  = max(0, py0 - HALF_), hi  = min(P_, py0 + HALF_);
        int clo = max(0, px0 - HALF_), chi = min(P_, px0 + HALF_);
        int rblo = lo / 15, rbhi = (hi - 1) / 15;
        int rlo = rblo * 15;
        int rhi = min(P_, (rbhi + 1) * 15);

        best = -1e30f; bi = 0x7fffffff;
        if (tid < NRB_ && (tid < rblo || tid > rbhi)) {
            best = g_pval[bc * NRB_ + tid];
            bi   = g_pidx[bc * NRB_ + tid];
        }
        int n = (rhi - rlo) * P_;
        for (int i = tid; i < n; i += 256) {
            int r  = i / P_;
            int cc = i - r * P_;
            r += rlo;
            int idx = r * P_ + cc;
            float v = pm[idx];
            if (r >= lo && r < hi && cc >= clo && cc < chi) v = 0.0f;
            if (v > best || (v == best && idx < bi)) { best = v; bi = idx; }
        }
        sv[tid] = best; si[tid] = bi;
        __syncthreads();
        for (int s = 128; s > 0; s >>= 1) {
            if (tid < s) {
                float ov = sv[tid + s];
                int   oi = si[tid + s];
                if (ov > sv[tid] || (ov == sv[tid] && oi < si[tid])) {
                    sv[tid] = ov; si[tid] = oi;
                }
            }
            __syncthreads();
        }

        if (tid == 0) {
            int idx1 = si[0];
            float val1 = sv[0];
            int py1 = idx1 / P_;
            int px1 = idx1 - py1 * P_;

            int pxs[K_] = {px0, px1};
            int pys[K_] = {py0, py1};
            float vals[K_] = {val0, val1};
#pragma unroll
            for (int j = 0; j < K_; j++) {
                g_selpx[bc * K_ + j] = pxs[j];
                g_selpy[bc * K_ + j] = pys[j];
                out[OFF_VALS + (c * K_ + j) * B_ + b] = vals[j];
                int o = OFF_OXY + ((c * K_ + j) * B_ + b) * 4;
                out[o + 0] = (float)pxs[j];
                out[o + 1] = (float)(pxs[j] + KER_ - 1);
                out[o + 2] = (float)pys[j];
                out[o + 3] = (float)(pys[j] + KER_ - 1);
            }
        }
    }

    gridbar();

    // ================= Phase D: patch gather (grid-stride over patches) =====
    for (int p = blk; p < 2176; p += GRID_) {
        const float* src;
        int Csrc, ch, c, j, b;
        long base;

        if (p < 64) {
            int t = p;
            ch = t & 1;  t >>= 1;
            b  = t & 7;  t >>= 3;
            j  = t & 1;  t >>= 1;
            c  = t;
            src = infeat; Csrc = 2;
            base = OFF_CLS + (long)p * 1024;
        } else if (p < 2112) {
            int t = p - 64;
            int local = t;
            ch = t & 63; t >>= 6;
            b  = t & 7;  t >>= 3;
            j  = t & 1;  t >>= 1;
            c  = t;
            src = feat; Csrc = CDA_;
            base = OFF_FEAT + (long)local * 1024;
        } else if (p < 2144) {
            int t = p - 2112;
            int local = t;
            ch = 0;
            b  = t & 7;  t >>= 3;
            j  = t & 1;  t >>= 1;
            c  = t;
            src = pesudo; Csrc = 1;
            base = OFF_PES + (long)local * 1024;
        } else {
            int t = p - 2144;
            int local = t;
            ch = 0;
            b  = t & 7;  t >>= 3;
            j  = t & 1;  t >>= 1;
            c  = t;
            src = labelT; Csrc = 1;
            base = OFF_TRUE + (long)local * 1024;
        }

        int sel = (b * 2 + c) * K_ + j;
        int px = g_selpx[sel];
        int py = g_selpy[sel];

        const float* s = src + (((long)b * Csrc + ch) * H_ + py) * H_ + px;

        int dy = tid >> 3;            // 256 threads, 4 consecutive floats each
        int dx = (tid & 7) * 4;
        const float* sp = s + dy * H_ + dx;
        float4 v;
        v.x = sp[0]; v.y = sp[1]; v.z = sp[2]; v.w = sp[3];
        *reinterpret_cast<float4*>(out + base + (long)tid * 4) = v;
    }
}

// ---------------------------------------------------------------------------
extern "C" void kernel_launch(void* const* d_in, const int* in_sizes, int n_in,
                              void* d_out, int out_size) {
    const float* infeat  = (const float*)d_in[0];
    const float* pesudo  = (const float*)d_in[1];
    const float* labelT  = (const float*)d_in[2];
    const float* featDA  = (const float*)d_in[3];
    float* out = (float*)d_out;

    k_fused<<<GRID_, 256>>>(infeat, pesudo, labelT, featDA, out);
}

// round 6
// speedup vs baseline: 2.9410x; 1.0641x over previous
#include <cuda_runtime.h>
#include <cuda_bf16.h>

// Problem constants
#define B_    8
#define H_    256
#define P_    225          // H - KER + 1
#define KER_  32
#define HALF_ 16
#define K_    2
#define CDA_  64
#define NBC_  16           // B * 2 classes
#define NRB_  15           // row-blocks per map (15 rows each)
#define GRID_ 740          // persistent blocks = 148 SMs * 5 blocks/SM

// Output section offsets (floats)
#define OFF_CLS   0
#define OFF_FEAT  65536
#define OFF_VALS  2162688
#define OFF_PES   2162720
#define OFF_TRUE  2195488
#define OFF_OXY   2228256

// Scratch
__device__ float g_rowsum[NBC_ * H_ * P_];
__device__ float g_pooled[NBC_ * P_ * P_];
__device__ float g_pval[NBC_ * NRB_];
__device__ int   g_pidx[NBC_ * NRB_];
__device__ int   g_selpx[NBC_ * K_];
__device__ int   g_selpy[NBC_ * K_];

// Grid barrier state. g_cnt returns to 0 after each barrier; g_gen grows
// monotonically (comparisons are relative) -> deterministic across replays.
__device__ unsigned g_cnt = 0;
__device__ unsigned g_gen = 0;

__device__ __forceinline__ void gridbar() {
    __threadfence();               // make this thread's writes globally visible
    __syncthreads();               // all block threads fenced
    if (threadIdx.x == 0) {
        unsigned eg = atomicAdd(&g_gen, 0u);       // entry generation
        unsigned my = atomicAdd(&g_cnt, 1u);
        if (my == GRID_ - 1) {
            atomicExch(&g_cnt, 0u);
            __threadfence();
            atomicAdd(&g_gen, 1u);                 // release
        } else {
            while (atomicAdd(&g_gen, 0u) == eg) __nanosleep(64);
            __threadfence();
        }
    }
    __syncthreads();
}

__global__ void __launch_bounds__(256, 5)
k_fused(const float* __restrict__ infeat,
        const float* __restrict__ pesudo,
        const float* __restrict__ labelT,
        const float* __restrict__ feat,
        float* __restrict__ out) {
    __shared__ float sc0[H_];
    __shared__ float sc1[H_];
    __shared__ float sv[256];
    __shared__ int   si[256];

    const int tid = threadIdx.x;
    const int lane = tid & 31;
    const int blk = blockIdx.x;

    // ================= Phase A: softmax + horizontal 32-window sums =========
    // win(x) = (S_w - scan_w[r-1]) + scan_{w+1}[r-1], chunk scans via shfl.
    for (int by = blk; by < B_ * H_; by += GRID_) {
        int b = by >> 8;
        int y = by & 255;

        float x0 = infeat[((b * 2 + 0) * H_ + y) * H_ + tid];
        float x1 = infeat[((b * 2 + 1) * H_ + y) * H_ + tid];
        float m  = fmaxf(x0, x1);
        float e0 = expf(x0 - m);
        float e1 = expf(x1 - m);
        float inv = 1.0f / (e0 + e1);
        float s0 = e0 * inv;
        float s1 = e1 * inv;

#pragma unroll
        for (int o = 1; o < 32; o <<= 1) {
            float t0 = __shfl_up_sync(0xffffffffu, s0, o);
            float t1 = __shfl_up_sync(0xffffffffu, s1, o);
            if (lane >= o) { s0 += t0; s1 += t1; }
        }
        __syncthreads();           // previous iteration's readers done
        sc0[tid] = s0;
        sc1[tid] = s1;
        __syncthreads();

        if (tid < P_) {
            int w = tid >> 5, r = tid & 31;
            float S0 = sc0[(w << 5) | 31];
            float S1 = sc1[(w << 5) | 31];
            float w0, w1;
            if (r == 0) { w0 = S0; w1 = S1; }
            else {
                w0 = (S0 - sc0[tid - 1]) + sc0[tid + 31];
                w1 = (S1 - sc1[tid - 1]) + sc1[tid + 31];
            }
            g_rowsum[((b * 2 + 0) * H_ + y) * P_ + tid] = w0;
            g_rowsum[((b * 2 + 1) * H_ + y) * P_ + tid] = w1;
        }
    }

    gridbar();

    // ================= Phase B: vertical pooling + per-slab argmax ==========
    if (blk < NBC_ * NRB_) {
        int bc = blk / NRB_;
        int chunk = blk % NRB_;
        const float* rs = g_rowsum + bc * H_ * P_;
        float* outp = g_pooled + bc * P_ * P_;

        float best = -1e30f;
        int bi = 0x7fffffff;

        if (tid < P_) {
            int py0 = chunk * 15;
            float s = 0.0f;
#pragma unroll
            for (int i = 0; i < KER_; i++) s += rs[(py0 + i) * P_ + tid];
            float v = s * (1.0f / 1024.0f);
            outp[py0 * P_ + tid] = v;
            best = v; bi = py0 * P_ + tid;
#pragma unroll
            for (int q = 1; q < 15; q++) {
                int py = py0 + q;
                s += rs[(py + 31) * P_ + tid] - rs[(py - 1) * P_ + tid];
                v = s * (1.0f / 1024.0f);
                outp[py * P_ + tid] = v;
                if (v > best) { best = v; bi = py * P_ + tid; }
            }
        }

        sv[tid] = best; si[tid] = bi;
        __syncthreads();
        for (int s = 128; s > 0; s >>= 1) {
            if (tid < s) {
                float ov = sv[tid + s];
                int   oi = si[tid + s];
                if (ov > sv[tid] || (ov == sv[tid] && oi < si[tid])) {
                    sv[tid] = ov; si[tid] = oi;
                }
            }
            __syncthreads();
        }
        if (tid == 0) {
            g_pval[bc * NRB_ + chunk] = sv[0];
            g_pidx[bc * NRB_ + chunk] = si[0];
        }
    }

    gridbar();

    // ================= Phase C: greedy top-2 selection (blocks 0..15) =======
    if (blk < NBC_) {
        int bc = blk;
        int b = bc >> 1;
        int c = bc & 1;
        const float* pm = g_pooled + bc * P_ * P_;

        // pass 1: reduce 15 partials
        float best = -1e30f;
        int bi = 0x7fffffff;
        if (tid < NRB_) {
            best = g_pval[bc * NRB_ + tid];
            bi   = g_pidx[bc * NRB_ + tid];
        }
        sv[tid] = best; si[tid] = bi;
        __syncthreads();
        for (int s = 128; s > 0; s >>= 1) {
            if (tid < s) {
                float ov = sv[tid + s];
                int   oi = si[tid + s];
                if (ov > sv[tid] || (ov == sv[tid] && oi < si[tid])) {
                    sv[tid] = ov; si[tid] = oi;
                }
            }
            __syncthreads();
        }
        int idx0 = si[0];
        float val0 = sv[0];
        int py0 = idx0 / P_;
        int px0 = idx0 - py0 * P_;
        __syncthreads();

        // pass 2: rescan affected row-blocks with suppression
        int lo  = max(0, py0 - HALF_), hi  = min(P_, py0 + HALF_);
        int clo = max(0, px0 - HALF_), chi = min(P_, px0 + HALF_);
        int rblo = lo / 15, rbhi = (hi - 1) / 15;
        int rlo = rblo * 15;
        int rhi = min(P_, (rbhi + 1) * 15);

        best = -1e30f; bi = 0x7fffffff;
        if (tid < NRB_ && (tid < rblo || tid > rbhi)) {
            best = g_pval[bc * NRB_ + tid];
            bi   = g_pidx[bc * NRB_ + tid];
        }
        int n = (rhi - rlo) * P_;
        for (int i = tid; i < n; i += 256) {
            int r  = i / P_;
            int cc = i - r * P_;
            r += rlo;
            int idx = r * P_ + cc;
            float v = pm[idx];
            if (r >= lo && r < hi && cc >= clo && cc < chi) v = 0.0f;
            if (v > best || (v == best && idx < bi)) { best = v; bi = idx; }
        }
        sv[tid] = best; si[tid] = bi;
        __syncthreads();
        for (int s = 128; s > 0; s >>= 1) {
            if (tid < s) {
                float ov = sv[tid + s];
                int   oi = si[tid + s];
                if (ov > sv[tid] || (ov == sv[tid] && oi < si[tid])) {
                    sv[tid] = ov; si[tid] = oi;
                }
            }
            __syncthreads();
        }

        if (tid == 0) {
            int idx1 = si[0];
            float val1 = sv[0];
            int py1 = idx1 / P_;
            int px1 = idx1 - py1 * P_;

            int pxs[K_] = {px0, px1};
            int pys[K_] = {py0, py1};
            float vals[K_] = {val0, val1};
#pragma unroll
            for (int j = 0; j < K_; j++) {
                g_selpx[bc * K_ + j] = pxs[j];
                g_selpy[bc * K_ + j] = pys[j];
                out[OFF_VALS + (c * K_ + j) * B_ + b] = vals[j];
                int o = OFF_OXY + ((c * K_ + j) * B_ + b) * 4;
                out[o + 0] = (float)pxs[j];
                out[o + 1] = (float)(pxs[j] + KER_ - 1);
                out[o + 2] = (float)pys[j];
                out[o + 3] = (float)(pys[j] + KER_ - 1);
            }
        }
    }

    gridbar();

    // ================= Phase D: patch gather (grid-stride over patches) =====
    for (int p = blk; p < 2176; p += GRID_) {
        const float* src;
        int Csrc, ch, c, j, b;
        long base;

        if (p < 64) {
            int t = p;
            ch = t & 1;  t >>= 1;
            b  = t & 7;  t >>= 3;
            j  = t & 1;  t >>= 1;
            c  = t;
            src = infeat; Csrc = 2;
            base = OFF_CLS + (long)p * 1024;
        } else if (p < 2112) {
            int t = p - 64;
            int local = t;
            ch = t & 63; t >>= 6;
            b  = t & 7;  t >>= 3;
            j  = t & 1;  t >>= 1;
            c  = t;
            src = feat; Csrc = CDA_;
            base = OFF_FEAT + (long)local * 1024;
        } else if (p < 2144) {
            int t = p - 2112;
            int local = t;
            ch = 0;
            b  = t & 7;  t >>= 3;
            j  = t & 1;  t >>= 1;
            c  = t;
            src = pesudo; Csrc = 1;
            base = OFF_PES + (long)local * 1024;
        } else {
            int t = p - 2144;
            int local = t;
            ch = 0;
            b  = t & 7;  t >>= 3;
            j  = t & 1;  t >>= 1;
            c  = t;
            src = labelT; Csrc = 1;
            base = OFF_TRUE + (long)local * 1024;
        }

        int sel = (b * 2 + c) * K_ + j;
        int px = g_selpx[sel];
        int py = g_selpy[sel];

        const float* s = src + (((long)b * Csrc + ch) * H_ + py) * H_ + px;

        int dy = tid >> 3;            // 256 threads, 4 consecutive floats each
        int dx = (tid & 7) * 4;
        const float* sp = s + dy * H_ + dx;
        float4 v;
        v.x = sp[0]; v.y = sp[1]; v.z = sp[2]; v.w = sp[3];
        *reinterpret_cast<float4*>(out + base + (long)tid * 4) = v;
    }
}

// ---------------------------------------------------------------------------
extern "C" void kernel_launch(void* const* d_in, const int* in_sizes, int n_in,
                              void* d_out, int out_size) {
    const float* infeat  = (const float*)d_in[0];
    const float* pesudo  = (const float*)d_in[1];
    const float* labelT  = (const float*)d_in[2];
    const float* featDA  = (const float*)d_in[3];
    float* out = (float*)d_out;

    k_fused<<<GRID_, 256>>>(infeat, pesudo, labelT, featDA, out);
}

// round 7
// speedup vs baseline: 2.9621x; 1.0072x over previous
#include <cuda_runtime.h>
#include <cuda_bf16.h>

// Problem constants
#define B_    8
#define H_    256
#define P_    225          // H - KER + 1
#define KER_  32
#define HALF_ 16
#define K_    2
#define CDA_  64
#define NBC_  16           // B * 2 classes
#define NRB_  15           // row-slabs per map (15 rows each)
#define NCH_  8            // 32-col chunks per map row (8*32 >= 225)
#define GRID_ 740          // persistent blocks = 148 SMs * 5 blocks/SM

// Output section offsets (floats)
#define OFF_CLS   0
#define OFF_FEAT  65536
#define OFF_VALS  2162688
#define OFF_PES   2162720
#define OFF_TRUE  2195488
#define OFF_OXY   2228256

// Scratch
__device__ float g_rowsum[NBC_ * H_ * P_];
__device__ float g_pooled[NBC_ * P_ * P_];
__device__ float g_cval[NBC_ * NRB_ * NCH_];   // per (map, slab, col-chunk) argmax partial
__device__ int   g_cidx[NBC_ * NRB_ * NCH_];
__device__ int   g_selpx[NBC_ * K_];
__device__ int   g_selpy[NBC_ * K_];

// Grid barrier: arrival = one RMW; release detection = volatile LOAD polling
// (no RMW storm). Generation compare is relative -> safe across graph replays.
__device__ unsigned g_cnt = 0;
__device__ unsigned g_gen = 0;

__device__ __forceinline__ void gridbar() {
    __threadfence();
    __syncthreads();
    if (threadIdx.x == 0) {
        volatile unsigned* vgen = (volatile unsigned*)&g_gen;
        unsigned eg = *vgen;                   // current generation (pre-release)
        unsigned my = atomicAdd(&g_cnt, 1u);   // arrive
        if (my == GRID_ - 1) {
            *(volatile unsigned*)&g_cnt = 0;
            __threadfence();
            atomicAdd(&g_gen, 1u);             // release
        } else {
            while (*vgen == eg) __nanosleep(32);
            __threadfence();
        }
    }
    __syncthreads();
}

// Warp argmax combine: max value, lowest flat index on ties.
__device__ __forceinline__ void warp_argmax(float& bv, int& bix) {
#pragma unroll
    for (int o = 16; o > 0; o >>= 1) {
        float ov = __shfl_xor_sync(0xffffffffu, bv, o);
        int   oi = __shfl_xor_sync(0xffffffffu, bix, o);
        if (ov > bv || (ov == bv && oi < bix)) { bv = ov; bix = oi; }
    }
}

__global__ void __launch_bounds__(256, 5)
k_fused(const float* __restrict__ infeat,
        const float* __restrict__ pesudo,
        const float* __restrict__ labelT,
        const float* __restrict__ feat,
        float* __restrict__ out) {
    __shared__ float sc0[H_];
    __shared__ float sc1[H_];
    __shared__ float sv[256];
    __shared__ int   si[256];

    const int tid = threadIdx.x;
    const int lane = tid & 31;
    const int warp = tid >> 5;
    const int blk = blockIdx.x;

    // ================= Phase A: softmax + horizontal 32-window sums =========
    for (int by = blk; by < B_ * H_; by += GRID_) {
        int b = by >> 8;
        int y = by & 255;

        float x0 = infeat[((b * 2 + 0) * H_ + y) * H_ + tid];
        float x1 = infeat[((b * 2 + 1) * H_ + y) * H_ + tid];
        float m  = fmaxf(x0, x1);
        float e0 = expf(x0 - m);
        float e1 = expf(x1 - m);
        float inv = 1.0f / (e0 + e1);
        float s0 = e0 * inv;
        float s1 = e1 * inv;

#pragma unroll
        for (int o = 1; o < 32; o <<= 1) {
            float t0 = __shfl_up_sync(0xffffffffu, s0, o);
            float t1 = __shfl_up_sync(0xffffffffu, s1, o);
            if (lane >= o) { s0 += t0; s1 += t1; }
        }
        __syncthreads();
        sc0[tid] = s0;
        sc1[tid] = s1;
        __syncthreads();

        if (tid < P_) {
            int w = tid >> 5, r = tid & 31;
            float S0 = sc0[(w << 5) | 31];
            float S1 = sc1[(w << 5) | 31];
            float w0, w1;
            if (r == 0) { w0 = S0; w1 = S1; }
            else {
                w0 = (S0 - sc0[tid - 1]) + sc0[tid + 31];
                w1 = (S1 - sc1[tid - 1]) + sc1[tid + 31];
            }
            g_rowsum[((b * 2 + 0) * H_ + y) * P_ + tid] = w0;
            g_rowsum[((b * 2 + 1) * H_ + y) * P_ + tid] = w1;
        }
    }

    gridbar();

    // ===== Phase B: vertical pooling + per-(slab, col-chunk) warp partials ===
    if (blk < NBC_ * NRB_) {
        int bc = blk / NRB_;
        int chunk = blk % NRB_;
        const float* rs = g_rowsum + bc * H_ * P_;
        float* outp = g_pooled + bc * P_ * P_;

        float best = -1e30f;
        int bi = 0x7fffffff;

        if (tid < P_) {
            int py0 = chunk * 15;
            float s = 0.0f;
#pragma unroll
            for (int i = 0; i < KER_; i++) s += rs[(py0 + i) * P_ + tid];
            float v = s * (1.0f / 1024.0f);
            outp[py0 * P_ + tid] = v;
            best = v; bi = py0 * P_ + tid;
#pragma unroll
            for (int q = 1; q < 15; q++) {
                int py = py0 + q;
                s += rs[(py + 31) * P_ + tid] - rs[(py - 1) * P_ + tid];
                v = s * (1.0f / 1024.0f);
                outp[py * P_ + tid] = v;
                if (v > best) { best = v; bi = py * P_ + tid; }
            }
        }

        warp_argmax(best, bi);       // warp w = cols [32w, 32w+32)
        if (lane == 0) {
            g_cval[(bc * NRB_ + chunk) * NCH_ + warp] = best;
            g_cidx[(bc * NRB_ + chunk) * NCH_ + warp] = bi;
        }
    }

    gridbar();

    // ================= Phase C: greedy top-2 selection (blocks 0..15) =======
    if (blk < NBC_) {
        int bc = blk;
        int b = bc >> 1;
        int c = bc & 1;
        const float* pm = g_pooled + bc * P_ * P_;

        // pass 1: reduce 120 chunk partials
        float best = -1e30f;
        int bi = 0x7fffffff;
        if (tid < NRB_ * NCH_) {
            best = g_cval[bc * NRB_ * NCH_ + tid];
            bi   = g_cidx[bc * NRB_ * NCH_ + tid];
        }
        sv[tid] = best; si[tid] = bi;
        __syncthreads();
        for (int s = 128; s > 0; s >>= 1) {
            if (tid < s) {
                float ov = sv[tid + s];
                int   oi = si[tid + s];
                if (ov > sv[tid] || (ov == sv[tid] && oi < si[tid])) {
                    sv[tid] = ov; si[tid] = oi;
                }
            }
            __syncthreads();
        }
        int idx0 = si[0];
        float val0 = sv[0];
        int py0 = idx0 / P_;
        int px0 = idx0 - py0 * P_;
        __syncthreads();

        // pass 2: untouched cell partials + MLP-batched rescan of touched region
        int lo  = max(0, py0 - HALF_), hi  = min(P_, py0 + HALF_);
        int clo = max(0, px0 - HALF_), chi = min(P_, px0 + HALF_);
        int rblo = lo / 15, rbhi = (hi - 1) / 15;
        int cblo = clo / 32, cbhi = (chi - 1) / 32;

        best = -1e30f; bi = 0x7fffffff;
        if (tid < NRB_ * NCH_) {
            int s = tid >> 3, cc = tid & 7;
            if (s < rblo || s > rbhi || cc < cblo || cc > cbhi) {
                best = g_cval[bc * NRB_ * NCH_ + tid];
                bi   = g_cidx[bc * NRB_ * NCH_ + tid];
            }
        }

        int r0 = rblo * 15, r1 = min(P_, (rbhi + 1) * 15);
        int c0 = cblo * 32, c1 = min(P_, (cbhi + 1) * 32);
        int W = c1 - c0;
        int n = (r1 - r0) * W;                 // <= 60*64 = 3840
        for (int i0 = tid; i0 < n; i0 += 256 * 8) {
#pragma unroll
            for (int u = 0; u < 8; u++) {
                int i = i0 + u * 256;
                if (i < n) {
                    int rr = i / W;
                    int col = c0 + (i - rr * W);
                    int row = r0 + rr;
                    int idx = row * P_ + col;
                    float v = pm[idx];
                    if (row >= lo && row < hi && col >= clo && col < chi) v = 0.0f;
                    if (v > best || (v == best && idx < bi)) { best = v; bi = idx; }
                }
            }
        }
        sv[tid] = best; si[tid] = bi;
        __syncthreads();
        for (int s = 128; s > 0; s >>= 1) {
            if (tid < s) {
                float ov = sv[tid + s];
                int   oi = si[tid + s];
                if (ov > sv[tid] || (ov == sv[tid] && oi < si[tid])) {
                    sv[tid] = ov; si[tid] = oi;
                }
            }
            __syncthreads();
        }

        if (tid == 0) {
            int idx1 = si[0];
            float val1 = sv[0];
            int py1 = idx1 / P_;
            int px1 = idx1 - py1 * P_;

            int pxs[K_] = {px0, px1};
            int pys[K_] = {py0, py1};
            float vals[K_] = {val0, val1};
#pragma unroll
            for (int j = 0; j < K_; j++) {
                g_selpx[bc * K_ + j] = pxs[j];
                g_selpy[bc * K_ + j] = pys[j];
                out[OFF_VALS + (c * K_ + j) * B_ + b] = vals[j];
                int o = OFF_OXY + ((c * K_ + j) * B_ + b) * 4;
                out[o + 0] = (float)pxs[j];
                out[o + 1] = (float)(pxs[j] + KER_ - 1);
                out[o + 2] = (float)pys[j];
                out[o + 3] = (float)(pys[j] + KER_ - 1);
            }
        }
    }

    gridbar();

    // ================= Phase D: patch gather (grid-stride over patches) =====
    for (int p = blk; p < 2176; p += GRID_) {
        const float* src;
        int Csrc, ch, c, j, b;
        long base;

        if (p < 64) {
            int t = p;
            ch = t & 1;  t >>= 1;
            b  = t & 7;  t >>= 3;
            j  = t & 1;  t >>= 1;
            c  = t;
            src = infeat; Csrc = 2;
            base = OFF_CLS + (long)p * 1024;
        } else if (p < 2112) {
            int t = p - 64;
            int local = t;
            ch = t & 63; t >>= 6;
            b  = t & 7;  t >>= 3;
            j  = t & 1;  t >>= 1;
            c  = t;
            src = feat; Csrc = CDA_;
            base = OFF_FEAT + (long)local * 1024;
        } else if (p < 2144) {
            int t = p - 2112;
            int local = t;
            ch = 0;
            b  = t & 7;  t >>= 3;
            j  = t & 1;  t >>= 1;
            c  = t;
            src = pesudo; Csrc = 1;
            base = OFF_PES + (long)local * 1024;
        } else {
            int t = p - 2144;
            int local = t;
            ch = 0;
            b  = t & 7;  t >>= 3;
            j  = t & 1;  t >>= 1;
            c  = t;
            src = labelT; Csrc = 1;
            base = OFF_TRUE + (long)local * 1024;
        }

        int sel = (b * 2 + c) * K_ + j;
        int px = g_selpx[sel];
        int py = g_selpy[sel];

        const float* s = src + (((long)b * Csrc + ch) * H_ + py) * H_ + px;

        int dy = tid >> 3;            // 256 threads, 4 consecutive floats each
        int dx = (tid & 7) * 4;
        const float* sp = s + dy * H_ + dx;
        float4 v;
        v.x = sp[0]; v.y = sp[1]; v.z = sp[2]; v.w = sp[3];
        *reinterpret_cast<float4*>(out + base + (long)tid * 4) = v;
    }
}

// ---------------------------------------------------------------------------
extern "C" void kernel_launch(void* const* d_in, const int* in_sizes, int n_in,
                              void* d_out, int out_size) {
    const float* infeat  = (const float*)d_in[0];
    const float* pesudo  = (const float*)d_in[1];
    const float* labelT  = (const float*)d_in[2];
    const float* featDA  = (const float*)d_in[3];
    float* out = (float*)d_out;

    k_fused<<<GRID_, 256>>>(infeat, pesudo, labelT, featDA, out);
}